// round 12
// baseline (speedup 1.0000x reference)
#include <cuda_runtime.h>
#include <math.h>

#define Bn 32
#define Hn 14
#define Wn 14
#define Cn 32
#define Kn 64
#define KSn 5
#define Pn 100      // 10x10 output positions
#define Mn 800      // ks*ks*C
#define Nn 196      // H*W
#define MS 10       // m-splits (800/10 = 80 = 5 chunks of 16)
#define MSP 80      // m per split
#define MCH 16      // m chunk

typedef unsigned long long ull;

// Scratch (device globals -- no allocations allowed)
__device__ float g_mup[Bn*Pn*Mn];        // mu patches   [b][p][m]
__device__ float g_dgp[Bn*Pn*Mn];        // diag patches [b][p][m]
__device__ float g_Gp[MS*Bn*Pn*Pn];      // Gram partials [ms][b][p][q]
__device__ float g_muP[MS*Bn*Pn*Kn];     // mu_out partials
__device__ float g_v1P[MS*Bn*Pn*Kn];     // diag_vals partials
__device__ float g_sp[Kn];               // softplus(w_sigma)
__device__ float g_wsq2[Mn*Kn];          // w^2 + sp, [m][k]

__device__ __forceinline__ ull dup2(float x) {
    ull r; asm("mov.b64 %0, {%1, %1};" : "=l"(r) : "f"(x)); return r;
}
__device__ __forceinline__ void unpack2(ull v, float &x, float &y) {
    asm("mov.b64 {%0, %1}, %2;" : "=f"(x), "=f"(y) : "l"(v));
}
__device__ __forceinline__ void fma2(ull &d, ull a, ull b) {
    asm("fma.rn.f32x2 %0, %1, %2, %0;" : "+l"(d) : "l"(a), "l"(b));
}

// ---------------------------------------------------------------------------
// Kernel 1: gather mu patches + Sigma diagonal patches; wsq2 = w^2 + sp; sp.
// ---------------------------------------------------------------------------
__global__ __launch_bounds__(256) void k_gather(const float* __restrict__ mu_in,
                                                const float* __restrict__ Sigma_in,
                                                const float* __restrict__ w_mu,
                                                const float* __restrict__ w_sigma) {
    int idx = blockIdx.x * 256 + threadIdx.x;
    if (idx < Mn * Kn) {
        int k = idx & 63;
        float w  = w_mu[idx];
        float sp = log1pf(expf(w_sigma[k]));
        g_wsq2[idx] = w * w + sp;
        if (idx < Kn) g_sp[idx] = sp;
    }
    if (idx >= Bn * Pn * Mn) return;
    int m  = idx % Mn;
    int bp = idx / Mn;
    int p  = bp % Pn;
    int b  = bp / Pn;
    int c  = m & 31;
    int ij = m >> 5;
    int j  = ij % KSn;
    int i  = ij / KSn;
    int y  = p / 10 + i;
    int x  = p % 10 + j;
    g_mup[idx] = mu_in[((b * Hn + y) * Wn + x) * Cn + c];
    int n = y * Wn + x;
    g_dgp[idx] = Sigma_in[(long long)b * (Nn * Nn * Cn) + (long long)n * (Nn * Cn + Cn) + c];
}

// ---------------------------------------------------------------------------
// Kernel 2: Gram partials. grid (32, 3 sym-tiles, 10 m-splits), 128 threads.
// Tile 64x64, micro 8p x 4q. Prefetch-pipelined staging.
// ---------------------------------------------------------------------------
__global__ __launch_bounds__(128) void k_gram() {
    __shared__ __align__(16) float As[MCH][68];
    __shared__ __align__(16) float Bs[MCH][68];
    int b   = blockIdx.x;
    int sel = blockIdx.y;
    int ms  = blockIdx.z;
    int pt = (sel == 2) ? 1 : 0;
    int qt = (sel == 0) ? 0 : 1;
    int t  = threadIdx.x;
    int qg = t & 15;       // q strip of 4
    int pg = t >> 4;       // p strip of 8
    const float* Abase = g_mup + (size_t)b * (Pn * Mn);

    // staging: thread = (row 0..63, half 0/1); 32 B contiguous per thread
    int srow = t >> 1;
    int sseg = (t & 1) * 8;
    int prowS = pt * 64 + srow; if (prowS > Pn - 1) prowS = Pn - 1;
    int qrowS = qt * 64 + srow; if (qrowS > Pn - 1) qrowS = Pn - 1;
    const float* ArS = Abase + (size_t)prowS * Mn + ms * MSP + sseg;
    const float* BrS = Abase + (size_t)qrowS * Mn + ms * MSP + sseg;

    ull acc[8][2] = {};

    float4 a0 = *(const float4*)(ArS);
    float4 a1 = *(const float4*)(ArS + 4);
    float4 b0 = *(const float4*)(BrS);
    float4 b1 = *(const float4*)(BrS + 4);

    for (int mc = 0; mc < MSP; mc += MCH) {
        As[sseg + 0][srow] = a0.x; As[sseg + 1][srow] = a0.y;
        As[sseg + 2][srow] = a0.z; As[sseg + 3][srow] = a0.w;
        As[sseg + 4][srow] = a1.x; As[sseg + 5][srow] = a1.y;
        As[sseg + 6][srow] = a1.z; As[sseg + 7][srow] = a1.w;
        Bs[sseg + 0][srow] = b0.x; Bs[sseg + 1][srow] = b0.y;
        Bs[sseg + 2][srow] = b0.z; Bs[sseg + 3][srow] = b0.w;
        Bs[sseg + 4][srow] = b1.x; Bs[sseg + 5][srow] = b1.y;
        Bs[sseg + 6][srow] = b1.z; Bs[sseg + 7][srow] = b1.w;
        __syncthreads();
        if (mc + MCH < MSP) {              // prefetch next chunk over compute
            a0 = *(const float4*)(ArS + mc + MCH);
            a1 = *(const float4*)(ArS + mc + MCH + 4);
            b0 = *(const float4*)(BrS + mc + MCH);
            b1 = *(const float4*)(BrS + mc + MCH + 4);
        }
#pragma unroll
        for (int ml = 0; ml < MCH; ml++) {
            ulonglong2 bb = *(ulonglong2*)&Bs[ml][qg * 4];
            float4 av0 = *(float4*)&As[ml][pg * 8];
            float4 av1 = *(float4*)&As[ml][pg * 8 + 4];
            ull d;
            d = dup2(av0.x); fma2(acc[0][0], d, bb.x); fma2(acc[0][1], d, bb.y);
            d = dup2(av0.y); fma2(acc[1][0], d, bb.x); fma2(acc[1][1], d, bb.y);
            d = dup2(av0.z); fma2(acc[2][0], d, bb.x); fma2(acc[2][1], d, bb.y);
            d = dup2(av0.w); fma2(acc[3][0], d, bb.x); fma2(acc[3][1], d, bb.y);
            d = dup2(av1.x); fma2(acc[4][0], d, bb.x); fma2(acc[4][1], d, bb.y);
            d = dup2(av1.y); fma2(acc[5][0], d, bb.x); fma2(acc[5][1], d, bb.y);
            d = dup2(av1.z); fma2(acc[6][0], d, bb.x); fma2(acc[6][1], d, bb.y);
            d = dup2(av1.w); fma2(acc[7][0], d, bb.x); fma2(acc[7][1], d, bb.y);
        }
        __syncthreads();
    }

    float* Gp = g_Gp + ((size_t)ms * Bn + b) * (Pn * Pn);
#pragma unroll
    for (int i = 0; i < 8; i++) {
        int p = pt * 64 + pg * 8 + i;
        if (p >= Pn) continue;
        float vv[4];
        unpack2(acc[i][0], vv[0], vv[1]);
        unpack2(acc[i][1], vv[2], vv[3]);
#pragma unroll
        for (int j = 0; j < 4; j++) {
            int q = qt * 64 + qg * 4 + j;
            if (q >= Pn) continue;
            Gp[p * Pn + q] = vv[j];
            if (sel == 1) Gp[q * Pn + p] = vv[j];
        }
    }
}

// ---------------------------------------------------------------------------
// Kernel 3: muv1 partials. grid (32, 2 z, 10 m-splits), 128 threads.
// Tile 128p(pad) x 64k, micro 8p x 8k. Prefetch-pipelined staging.
// ---------------------------------------------------------------------------
__global__ __launch_bounds__(128) void k_muv1(const float* __restrict__ w_mu) {
    __shared__ __align__(16) float As[MCH][132];
    __shared__ __align__(16) float Ws[MCH][68];
    int b  = blockIdx.x;
    int z  = blockIdx.y;
    int ms = blockIdx.z;
    const float* A = (z == 0 ? g_mup : g_dgp) + (size_t)b * (Pn * Mn);
    const float* W = (z == 0) ? w_mu : g_wsq2;
    int t  = threadIdx.x;
    int kg = t & 7;
    int pg = t >> 3;

    int prow = t; if (prow > Pn - 1) prow = Pn - 1;
    const float* Arow = A + (size_t)prow * Mn + ms * MSP;
    // W staging coords: thread covers 2 (m, k4) pairs
    int wm0 = t >> 4, wk0 = (t & 15) * 4;              // m 0..7
    int wm1 = (t + 128) >> 4, wk1 = wk0;               // m 8..15
    const float* Wbase = W + (size_t)(ms * MSP) * Kn;

    ull acc[8][4] = {};

    float4 pa[4], pw0, pw1;
#pragma unroll
    for (int r = 0; r < 4; r++) pa[r] = *(const float4*)(Arow + r * 4);
    pw0 = *(const float4*)(Wbase + (size_t)wm0 * Kn + wk0);
    pw1 = *(const float4*)(Wbase + (size_t)wm1 * Kn + wk1);

    for (int mc = 0; mc < MSP; mc += MCH) {
#pragma unroll
        for (int r = 0; r < 4; r++) {
            As[r * 4 + 0][t] = pa[r].x; As[r * 4 + 1][t] = pa[r].y;
            As[r * 4 + 2][t] = pa[r].z; As[r * 4 + 3][t] = pa[r].w;
        }
        *(float4*)&Ws[wm0][wk0] = pw0;
        *(float4*)&Ws[wm1][wk1] = pw1;
        __syncthreads();
        if (mc + MCH < MSP) {
#pragma unroll
            for (int r = 0; r < 4; r++) pa[r] = *(const float4*)(Arow + mc + MCH + r * 4);
            pw0 = *(const float4*)(Wbase + (size_t)(mc + MCH + wm0) * Kn + wk0);
            pw1 = *(const float4*)(Wbase + (size_t)(mc + MCH + wm1) * Kn + wk1);
        }
#pragma unroll
        for (int ml = 0; ml < MCH; ml++) {
            ulonglong2 w0 = *(ulonglong2*)&Ws[ml][kg * 8];
            ulonglong2 w1 = *(ulonglong2*)&Ws[ml][kg * 8 + 4];
            float4 av0 = *(float4*)&As[ml][pg * 8];
            float4 av1 = *(float4*)&As[ml][pg * 8 + 4];
            ull d;
            d = dup2(av0.x); fma2(acc[0][0], d, w0.x); fma2(acc[0][1], d, w0.y); fma2(acc[0][2], d, w1.x); fma2(acc[0][3], d, w1.y);
            d = dup2(av0.y); fma2(acc[1][0], d, w0.x); fma2(acc[1][1], d, w0.y); fma2(acc[1][2], d, w1.x); fma2(acc[1][3], d, w1.y);
            d = dup2(av0.z); fma2(acc[2][0], d, w0.x); fma2(acc[2][1], d, w0.y); fma2(acc[2][2], d, w1.x); fma2(acc[2][3], d, w1.y);
            d = dup2(av0.w); fma2(acc[3][0], d, w0.x); fma2(acc[3][1], d, w0.y); fma2(acc[3][2], d, w1.x); fma2(acc[3][3], d, w1.y);
            d = dup2(av1.x); fma2(acc[4][0], d, w0.x); fma2(acc[4][1], d, w0.y); fma2(acc[4][2], d, w1.x); fma2(acc[4][3], d, w1.y);
            d = dup2(av1.y); fma2(acc[5][0], d, w0.x); fma2(acc[5][1], d, w0.y); fma2(acc[5][2], d, w1.x); fma2(acc[5][3], d, w1.y);
            d = dup2(av1.z); fma2(acc[6][0], d, w0.x); fma2(acc[6][1], d, w0.y); fma2(acc[6][2], d, w1.x); fma2(acc[6][3], d, w1.y);
            d = dup2(av1.w); fma2(acc[7][0], d, w0.x); fma2(acc[7][1], d, w0.y); fma2(acc[7][2], d, w1.x); fma2(acc[7][3], d, w1.y);
        }
        __syncthreads();
    }

    float* outP = ((z == 0) ? g_muP : g_v1P) + ((size_t)ms * Bn + b) * (Pn * Kn);
    int k0 = kg * 8;
#pragma unroll
    for (int i = 0; i < 8; i++) {
        int p = pg * 8 + i;
        if (p >= Pn) continue;
        float4 v0, v1;
        unpack2(acc[i][0], v0.x, v0.y);
        unpack2(acc[i][1], v0.z, v0.w);
        unpack2(acc[i][2], v1.x, v1.y);
        unpack2(acc[i][3], v1.z, v1.w);
        *(float4*)(outP + (size_t)p * Kn + k0)     = v0;
        *(float4*)(outP + (size_t)p * Kn + k0 + 4) = v1;
    }
}

// ---------------------------------------------------------------------------
// Kernel 4: sum the MS partials for mu_out only (skipped if !write_mu).
// ---------------------------------------------------------------------------
__global__ __launch_bounds__(256) void k_fix(float* __restrict__ mu_out) {
    int idx = blockIdx.x * 256 + threadIdx.x;
    if (idx >= Bn * Pn * Kn) return;
    const int STR = Bn * Pn * Kn;
    float sm = 0.f;
#pragma unroll
    for (int ms = 0; ms < MS; ms++) sm += g_muP[ms * STR + idx];
    mu_out[idx] = sm;
}

// ---------------------------------------------------------------------------
// Kernel 5: Sigma_out [32,100,100,64]. One thread per (b,p,q): 64 k's.
// Diagonal threads sum v1 partials inline (fused k_fix for v1).
// ---------------------------------------------------------------------------
__global__ __launch_bounds__(256) void k_sigma(float* __restrict__ sigma_out) {
    __shared__ float sp_s[Kn];
    int t = threadIdx.x;
    if (t < 16) ((float4*)sp_s)[t] = ((const float4*)g_sp)[t];
    __syncthreads();

    int bpq = blockIdx.x * 256 + t;
    if (bpq >= Bn * Pn * Pn) return;
    int q  = bpq % Pn;
    int bp = bpq / Pn;
    int p  = bp % Pn;

    const int GSTR = Bn * Pn * Pn;
    float g = 0.f;
#pragma unroll
    for (int ms = 0; ms < MS; ms++) g += g_Gp[ms * GSTR + bpq];

    bool diag = (p == q);
    const float* vrow = g_v1P + (size_t)bp * Kn;   // ms=0 slice; stride VSTR per split
    const int VSTR = Bn * Pn * Kn;
    float* orow = sigma_out + (size_t)bpq * Kn;

#pragma unroll 4
    for (int j = 0; j < 16; j++) {
        float4 s = *(const float4*)&sp_s[j * 4];
        float4 v;
        v.x = s.x * g; v.y = s.y * g; v.z = s.z * g; v.w = s.w * g;
        if (diag) {
#pragma unroll
            for (int ms = 0; ms < MS; ms++) {
                float4 d = *(const float4*)(vrow + (size_t)ms * VSTR + j * 4);
                v.x += d.x; v.y += d.y; v.z += d.z; v.w += d.w;
            }
        }
        v.x = isfinite(v.x) ? v.x : 0.f;
        v.y = isfinite(v.y) ? v.y : 0.f;
        v.z = isfinite(v.z) ? v.z : 0.f;
        v.w = isfinite(v.w) ? v.w : 0.f;
        int dq = q - j * 4;
        if (dq == 0)      v.x = fabsf(v.x);
        else if (dq == 1) v.y = fabsf(v.y);
        else if (dq == 2) v.z = fabsf(v.z);
        else if (dq == 3) v.w = fabsf(v.w);
        *(float4*)(orow + j * 4) = v;
    }
}

// ---------------------------------------------------------------------------
extern "C" void kernel_launch(void* const* d_in, const int* in_sizes, int n_in,
                              void* d_out, int out_size) {
    const float* mu_in    = (const float*)d_in[0];
    const float* Sigma_in = (const float*)d_in[1];
    const float* w_mu     = (const float*)d_in[2];
    const float* w_sigma  = (const float*)d_in[3];
    float* out = (float*)d_out;

    const long long sigma_elems = (long long)Bn * Pn * Pn * Kn;
    long long sigma_off = (long long)out_size - sigma_elems;
    if (sigma_off < 0) sigma_off = 0;
    int write_mu = (sigma_off >= (long long)Bn * Pn * Kn) ? 1 : 0;
    float* mu_out    = out;
    float* sigma_out = out + sigma_off;

    k_gather<<<(Bn * Pn * Mn + 255) / 256, 256>>>(mu_in, Sigma_in, w_mu, w_sigma);
    k_gram<<<dim3(Bn, 3, MS), 128>>>();
    k_muv1<<<dim3(Bn, 2, MS), 128>>>(w_mu);
    if (write_mu)
        k_fix<<<(Bn * Pn * Kn + 255) / 256, 256>>>(mu_out);
    k_sigma<<<(Bn * Pn * Pn + 255) / 256, 256>>>(sigma_out);
}